// round 2
// baseline (speedup 1.0000x reference)
#include <cuda_runtime.h>
#include <cstdint>

// Problem constants (fixed shapes: pred/target = [4, 8192, 3] fp32)
#define NB      4
#define NPTS    8192
#define THREADS 256
#define APT     8                      // a-points per thread (4 f32x2 pairs)
#define A_PER_BLOCK (THREADS * APT)    // 2048
#define ACH     4                      // a chunks  (4 * 2048 = 8192)
#define TCH     4                      // target chunks
#define TPCH    2048                   // targets per chunk
#define TILE    1024                   // staged targets per shared tile (32 KB)

// Partial per-a-point mins: [dir*4+b][tchunk][NPTS]  (1 MB scratch, static)
__device__ float g_smin[2 * NB * TCH * NPTS];

typedef unsigned long long u64;

__device__ __forceinline__ u64 pack2(float lo, float hi) {
    u64 r; asm("mov.b64 %0, {%1, %2};" : "=l"(r) : "f"(lo), "f"(hi)); return r;
}
__device__ __forceinline__ void unpack2(u64 v, float& lo, float& hi) {
    asm("mov.b64 {%0, %1}, %2;" : "=f"(lo), "=f"(hi) : "l"(v));
}
// Packed fp32x2 FMA (Blackwell): two fp32 FMAs per fma-pipe slot.
__device__ __forceinline__ u64 fma2(u64 a, u64 b, u64 c) {
    u64 d; asm("fma.rn.f32x2 %0, %1, %2, %3;" : "=l"(d) : "l"(a), "l"(b), "l"(c)); return d;
}

// For each a-point in this block's chunk: min over this block's target chunk of
//   s = 0.5*||b||^2 - a.b     (dist^2 = ||a||^2 + 2s, monotone in s)
__global__ void __launch_bounds__(THREADS, 1)
chamfer_min_kernel(const float* __restrict__ pred, const float* __restrict__ tgt) {
    __shared__ float4 sh[TILE * 2];   // [2j] = (qx,qx,qy,qy), [2j+1] = (qz,qz,h,h)

    const int tchunk = blockIdx.x;
    const int achunk = blockIdx.y;
    const int dirb   = blockIdx.z;        // dir*4 + batch
    const int dir    = dirb >> 2;
    const int b      = dirb & 3;

    const float* Ap = (dir == 0 ? pred : tgt) + (size_t)b * NPTS * 3;
    const float* Bp = (dir == 0 ? tgt : pred) + (size_t)b * NPTS * 3;

    const int tid   = threadIdx.x;
    const int abase = achunk * A_PER_BLOCK + tid * APT;

    // Register-resident negated a-points, packed 2-per-f32x2.
    u64 nax[APT / 2], nay[APT / 2], naz[APT / 2];
    float mn[APT];
#pragma unroll
    for (int k = 0; k < APT / 2; k++) {
        int i0 = abase + 2 * k;
        float x0 = Ap[3 * i0 + 0], y0 = Ap[3 * i0 + 1], z0 = Ap[3 * i0 + 2];
        float x1 = Ap[3 * i0 + 3], y1 = Ap[3 * i0 + 4], z1 = Ap[3 * i0 + 5];
        nax[k] = pack2(-x0, -x1);
        nay[k] = pack2(-y0, -y1);
        naz[k] = pack2(-z0, -z1);
        mn[2 * k]     = __int_as_float(0x7f800000);  // +inf
        mn[2 * k + 1] = __int_as_float(0x7f800000);
    }

    const ulonglong2* sp = reinterpret_cast<const ulonglong2*>(sh);

    for (int tile = 0; tile < TPCH / TILE; tile++) {
        const int tb = tchunk * TPCH + tile * TILE;
        __syncthreads();  // protect previous tile before overwrite
        for (int j = tid; j < TILE; j += THREADS) {
            int gj = tb + j;
            float x = Bp[3 * gj + 0];
            float y = Bp[3 * gj + 1];
            float z = Bp[3 * gj + 2];
            float h = 0.5f * fmaf(x, x, fmaf(y, y, z * z));
            sh[2 * j]     = make_float4(x, x, y, y);  // pre-duplicated for f32x2 broadcast
            sh[2 * j + 1] = make_float4(z, z, h, h);
        }
        __syncthreads();

#pragma unroll 2
        for (int j = 0; j < TILE; j++) {
            ulonglong2 v0 = sp[2 * j];       // LDS.128: qx2, qy2 (broadcast across warp)
            ulonglong2 v1 = sp[2 * j + 1];   // LDS.128: qz2, h2
            u64 qx2 = v0.x, qy2 = v0.y, qz2 = v1.x, h2 = v1.y;
#pragma unroll
            for (int k = 0; k < APT / 2; k++) {
                u64 s = fma2(naz[k], qz2, h2);
                s = fma2(nay[k], qy2, s);
                s = fma2(nax[k], qx2, s);
                float s0, s1; unpack2(s, s0, s1);
                mn[2 * k]     = fminf(mn[2 * k], s0);     // FMNMX on alu pipe, dual-issues
                mn[2 * k + 1] = fminf(mn[2 * k + 1], s1);
            }
        }
    }

    float* dst = &g_smin[((size_t)dirb * TCH + tchunk) * NPTS];
#pragma unroll
    for (int i = 0; i < APT; i++) dst[abase + i] = mn[i];
}

__global__ void zero_out_kernel(float* out) { *out = 0.0f; }

// Combine t-chunk partial mins, add ||a||^2, mean-reduce, atomic-accumulate scalar.
__global__ void chamfer_reduce_kernel(const float* __restrict__ pred,
                                      const float* __restrict__ tgt,
                                      float* __restrict__ out) {
    __shared__ float red[THREADS];
    const int dirb = blockIdx.x;   // 0..7
    const int dir  = dirb >> 2;
    const int b    = dirb & 3;
    const float* Ap   = (dir == 0 ? pred : tgt) + (size_t)b * NPTS * 3;
    const float* base = &g_smin[(size_t)dirb * TCH * NPTS];

    float sum = 0.0f;
    for (int a = threadIdx.x; a < NPTS; a += THREADS) {
        float s = base[a];
#pragma unroll
        for (int t = 1; t < TCH; t++) s = fminf(s, base[(size_t)t * NPTS + a]);
        float x = Ap[3 * a + 0], y = Ap[3 * a + 1], z = Ap[3 * a + 2];
        sum += x * x + y * y + z * z + 2.0f * s;   // min dist^2 for this point
    }
    red[threadIdx.x] = sum;
    __syncthreads();
    for (int off = THREADS / 2; off > 0; off >>= 1) {
        if (threadIdx.x < off) red[threadIdx.x] += red[threadIdx.x + off];
        __syncthreads();
    }
    if (threadIdx.x == 0)
        atomicAdd(out, red[0] * (1.0f / ((float)NB * (float)NPTS)));
}

extern "C" void kernel_launch(void* const* d_in, const int* in_sizes, int n_in,
                              void* d_out, int out_size) {
    const float* pred = (const float*)d_in[0];
    const float* tgt  = (const float*)d_in[1];
    float* out = (float*)d_out;
    (void)in_sizes; (void)n_in; (void)out_size;

    zero_out_kernel<<<1, 1>>>(out);
    dim3 grid(TCH, ACH, 2 * NB);   // 4 x 4 x 8 = 128 CTAs, one wave
    chamfer_min_kernel<<<grid, THREADS>>>(pred, tgt);
    chamfer_reduce_kernel<<<2 * NB, THREADS>>>(pred, tgt, out);
}

// round 3
// speedup vs baseline: 1.0308x; 1.0308x over previous
#include <cuda_runtime.h>
#include <cstdint>

// Fixed shapes: pred/target = [4, 8192, 3] fp32
#define NB      4
#define NPTS    8192
#define THREADS 256
#define APT     8                      // a-points per thread (4 f32x2 pairs)
#define A_PER_BLOCK (THREADS * APT)    // 2048
#define ACH     4                      // a chunks  (4 * 2048 = 8192)
#define TCH     4                      // target chunks
#define TPCH    2048                   // targets per chunk
#define TILE    1024                   // staged targets per shared tile (32 KB)
#define NDIRB   (2 * NB)               // 8
#define CTAS_PER_DIRB (ACH * TCH)      // 16

// Scratch (static device allocations — allowed)
__device__ float        g_smin[NDIRB * TCH * NPTS];  // 1 MB partial mins
__device__ float        g_sums[NDIRB];
__device__ unsigned int g_cnt[NDIRB];                // zero-init; reset each run
__device__ unsigned int g_cnt2;                      // zero-init; reset each run

typedef unsigned long long u64;

__device__ __forceinline__ u64 pack2(float lo, float hi) {
    u64 r; asm("mov.b64 %0, {%1, %2};" : "=l"(r) : "f"(lo), "f"(hi)); return r;
}
__device__ __forceinline__ void unpack2(u64 v, float& lo, float& hi) {
    asm("mov.b64 {%0, %1}, %2;" : "=f"(lo), "=f"(hi) : "l"(v));
}
// Packed fp32x2 FMA (Blackwell)
__device__ __forceinline__ u64 fma2(u64 a, u64 b, u64 c) {
    u64 d; asm("fma.rn.f32x2 %0, %1, %2, %3;" : "=l"(d) : "l"(a), "l"(b), "l"(c)); return d;
}

// Fused: per-(dirb,achunk,tchunk) min tiles + last-CTA-per-dirb reduction +
// global last-CTA final combine. Single launch, graph-capturable.
__global__ void __launch_bounds__(THREADS, 1)
chamfer_fused_kernel(const float* __restrict__ pred, const float* __restrict__ tgt,
                     float* __restrict__ out) {
    __shared__ float4 sh[TILE * 2];   // [2j]=(qx,qx,qy,qy), [2j+1]=(qz,qz,h,h)
    __shared__ int    s_last;
    __shared__ float  s_red[THREADS];

    const int tchunk = blockIdx.x;
    const int achunk = blockIdx.y;
    const int dirb   = blockIdx.z;        // dir*4 + batch
    const int dir    = dirb >> 2;
    const int b      = dirb & 3;

    const float* Ap = (dir == 0 ? pred : tgt) + (size_t)b * NPTS * 3;
    const float* Bp = (dir == 0 ? tgt : pred) + (size_t)b * NPTS * 3;

    const int tid   = threadIdx.x;
    const int abase = achunk * A_PER_BLOCK + tid * APT;

    // Register-resident negated a-points, packed 2-per-f32x2.
    u64 nax[APT / 2], nay[APT / 2], naz[APT / 2];
    float mn[APT];
#pragma unroll
    for (int k = 0; k < APT / 2; k++) {
        int i0 = abase + 2 * k;
        float x0 = Ap[3 * i0 + 0], y0 = Ap[3 * i0 + 1], z0 = Ap[3 * i0 + 2];
        float x1 = Ap[3 * i0 + 3], y1 = Ap[3 * i0 + 4], z1 = Ap[3 * i0 + 5];
        nax[k] = pack2(-x0, -x1);
        nay[k] = pack2(-y0, -y1);
        naz[k] = pack2(-z0, -z1);
        mn[2 * k]     = __int_as_float(0x7f800000);
        mn[2 * k + 1] = __int_as_float(0x7f800000);
    }

    const ulonglong2* sp = reinterpret_cast<const ulonglong2*>(sh);

    for (int tile = 0; tile < TPCH / TILE; tile++) {
        const int tb = tchunk * TPCH + tile * TILE;
        __syncthreads();
        for (int j = tid; j < TILE; j += THREADS) {
            int gj = tb + j;
            float x = Bp[3 * gj + 0];
            float y = Bp[3 * gj + 1];
            float z = Bp[3 * gj + 2];
            float h = 0.5f * fmaf(x, x, fmaf(y, y, z * z));
            sh[2 * j]     = make_float4(x, x, y, y);
            sh[2 * j + 1] = make_float4(z, z, h, h);
        }
        __syncthreads();

#pragma unroll 2
        for (int j = 0; j < TILE; j++) {
            ulonglong2 v0 = sp[2 * j];       // qx2, qy2 (warp-broadcast LDS.128)
            ulonglong2 v1 = sp[2 * j + 1];   // qz2, h2
            u64 qx2 = v0.x, qy2 = v0.y, qz2 = v1.x, h2 = v1.y;
#pragma unroll
            for (int k = 0; k < APT / 2; k++) {
                u64 s = fma2(naz[k], qz2, h2);
                s = fma2(nay[k], qy2, s);
                s = fma2(nax[k], qx2, s);
                float s0, s1; unpack2(s, s0, s1);
                mn[2 * k]     = fminf(mn[2 * k], s0);
                mn[2 * k + 1] = fminf(mn[2 * k + 1], s1);
            }
        }
    }

    // Publish partial mins:  s = 0.5||b||^2 - a.b  (dist^2 = ||a||^2 + 2s)
    {
        float* dst = &g_smin[((size_t)dirb * TCH + tchunk) * NPTS];
#pragma unroll
        for (int i = 0; i < APT; i++) dst[abase + i] = mn[i];
    }

    // Arrive on dirb group counter; elect last CTA of this dirb.
    __threadfence();
    if (tid == 0) {
        unsigned int old = atomicAdd(&g_cnt[dirb], 1u);
        s_last = (old == CTAS_PER_DIRB - 1);
    }
    __syncthreads();
    if (!s_last) return;
    __threadfence();  // acquire: make all g_smin writes for this dirb visible

    // Per-dirb reduction: combine tchunk mins, add ||a||^2, sum over points.
    const float* base = &g_smin[(size_t)dirb * TCH * NPTS];
    float sum = 0.0f;
    for (int a = tid; a < NPTS; a += THREADS) {
        float s = base[a];
#pragma unroll
        for (int t = 1; t < TCH; t++) s = fminf(s, base[(size_t)t * NPTS + a]);
        float x = Ap[3 * a + 0], y = Ap[3 * a + 1], z = Ap[3 * a + 2];
        sum += fmaf(x, x, fmaf(y, y, z * z)) + 2.0f * s;
    }
    s_red[tid] = sum;
    __syncthreads();
    for (int off = THREADS / 2; off > 0; off >>= 1) {
        if (tid < off) s_red[tid] += s_red[tid + off];
        __syncthreads();
    }

    if (tid == 0) {
        g_sums[dirb] = s_red[0];
        __threadfence();
        unsigned int old2 = atomicAdd(&g_cnt2, 1u);
        if (old2 == NDIRB - 1) {
            __threadfence();
            float total = 0.0f;
#pragma unroll
            for (int d = 0; d < NDIRB; d++) total += g_sums[d];
            *out = total * (1.0f / ((float)NB * (float)NPTS));
            // Reset counters for the next graph replay.
#pragma unroll
            for (int d = 0; d < NDIRB; d++) g_cnt[d] = 0u;
            g_cnt2 = 0u;
            __threadfence();
        }
    }
}

extern "C" void kernel_launch(void* const* d_in, const int* in_sizes, int n_in,
                              void* d_out, int out_size) {
    const float* pred = (const float*)d_in[0];
    const float* tgt  = (const float*)d_in[1];
    float* out = (float*)d_out;
    (void)in_sizes; (void)n_in; (void)out_size;

    dim3 grid(TCH, ACH, NDIRB);   // 4 x 4 x 8 = 128 CTAs, one wave
    chamfer_fused_kernel<<<grid, THREADS>>>(pred, tgt, out);
}

// round 4
// speedup vs baseline: 1.0498x; 1.0184x over previous
#include <cuda_runtime.h>
#include <cstdint>

// Fixed shapes: pred/target = [4, 8192, 3] fp32
#define NB      4
#define NPTS    8192
#define THREADS 128
#define APT     8                      // a-points per thread (4 f32x2 packs)
#define A_PER_BLOCK (THREADS * APT)    // 1024
#define ACH     8                      // a chunks  (8 * 1024 = 8192)
#define TCH     8                      // target chunks
#define TPCH    1024                   // targets per chunk = one shared tile
#define TILE    TPCH
#define NDIRB   (2 * NB)               // 8
#define CTAS_PER_DIRB (ACH * TCH)      // 64

// Scratch (static device allocations — allowed)
__device__ float        g_smin[NDIRB * TCH * NPTS];  // 2 MB partial mins
__device__ float        g_sums[NDIRB];
__device__ unsigned int g_cnt[NDIRB];                // zero-init; reset each replay
__device__ unsigned int g_cnt2;                      // zero-init; reset each replay

typedef unsigned long long u64;

__device__ __forceinline__ u64 pack2(float lo, float hi) {
    u64 r; asm("mov.b64 %0, {%1, %2};" : "=l"(r) : "f"(lo), "f"(hi)); return r;
}
__device__ __forceinline__ void unpack2(u64 v, float& lo, float& hi) {
    asm("mov.b64 {%0, %1}, %2;" : "=f"(lo), "=f"(hi) : "l"(v));
}
// Packed fp32x2 FMA (Blackwell)
__device__ __forceinline__ u64 fma2(u64 a, u64 b, u64 c) {
    u64 d; asm("fma.rn.f32x2 %0, %1, %2, %3;" : "=l"(d) : "l"(a), "l"(b), "l"(c)); return d;
}

__global__ void __launch_bounds__(THREADS, 4)
chamfer_fused_kernel(const float* __restrict__ pred, const float* __restrict__ tgt,
                     float* __restrict__ out) {
    __shared__ float4 sh[TILE * 2];   // [2j]=(qx,qx,qy,qy), [2j+1]=(qz,qz,h,h) = 32 KB
    __shared__ int    s_last;
    __shared__ float  s_red[THREADS];

    const int tchunk = blockIdx.x;
    const int achunk = blockIdx.y;
    const int dirb   = blockIdx.z;        // dir*4 + batch
    const int dir    = dirb >> 2;
    const int b      = dirb & 3;

    const float* Ap = (dir == 0 ? pred : tgt) + (size_t)b * NPTS * 3;
    const float* Bp = (dir == 0 ? tgt : pred) + (size_t)b * NPTS * 3;

    const int tid   = threadIdx.x;
    const int abase = achunk * A_PER_BLOCK + tid * APT;

    // Stage this CTA's target tile: pre-duplicated for f32x2 broadcast.
    {
        const int tb = tchunk * TPCH;
        for (int j = tid; j < TILE; j += THREADS) {
            int gj = tb + j;
            float x = Bp[3 * gj + 0];
            float y = Bp[3 * gj + 1];
            float z = Bp[3 * gj + 2];
            float h = 0.5f * fmaf(x, x, fmaf(y, y, z * z));
            sh[2 * j]     = make_float4(x, x, y, y);
            sh[2 * j + 1] = make_float4(z, z, h, h);
        }
    }

    // Register-resident negated a-points, packed 2-per-f32x2.
    u64 nax[APT / 2], nay[APT / 2], naz[APT / 2];
    float mn[APT];
#pragma unroll
    for (int k = 0; k < APT / 2; k++) {
        int i0 = abase + 2 * k;
        float x0 = Ap[3 * i0 + 0], y0 = Ap[3 * i0 + 1], z0 = Ap[3 * i0 + 2];
        float x1 = Ap[3 * i0 + 3], y1 = Ap[3 * i0 + 4], z1 = Ap[3 * i0 + 5];
        nax[k] = pack2(-x0, -x1);
        nay[k] = pack2(-y0, -y1);
        naz[k] = pack2(-z0, -z1);
        mn[2 * k]     = __int_as_float(0x7f800000);
        mn[2 * k + 1] = __int_as_float(0x7f800000);
    }

    __syncthreads();

    const ulonglong2* sp = reinterpret_cast<const ulonglong2*>(sh);
#pragma unroll 4
    for (int j = 0; j < TILE; j++) {
        ulonglong2 v0 = sp[2 * j];       // qx2, qy2 (warp-broadcast LDS.128)
        ulonglong2 v1 = sp[2 * j + 1];   // qz2, h2
        u64 qx2 = v0.x, qy2 = v0.y, qz2 = v1.x, h2 = v1.y;
#pragma unroll
        for (int k = 0; k < APT / 2; k++) {
            u64 s = fma2(naz[k], qz2, h2);
            s = fma2(nay[k], qy2, s);
            s = fma2(nax[k], qx2, s);
            float s0, s1; unpack2(s, s0, s1);
            mn[2 * k]     = fminf(mn[2 * k], s0);
            mn[2 * k + 1] = fminf(mn[2 * k + 1], s1);
        }
    }

    // Publish partial mins:  s = 0.5||b||^2 - a.b  (dist^2 = ||a||^2 + 2s)
    {
        float* dst = &g_smin[((size_t)dirb * TCH + tchunk) * NPTS];
#pragma unroll
        for (int i = 0; i < APT; i++) dst[abase + i] = mn[i];
    }

    // Elect last CTA of this dirb group.
    __threadfence();
    if (tid == 0) {
        unsigned int old = atomicAdd(&g_cnt[dirb], 1u);
        s_last = (old == CTAS_PER_DIRB - 1);
    }
    __syncthreads();
    if (!s_last) return;
    __threadfence();  // acquire all g_smin writes for this dirb

    // Per-dirb tail: combine tchunk mins, add ||a||^2, sum over points.
    const float* base = &g_smin[(size_t)dirb * TCH * NPTS];
    float sum = 0.0f;
    for (int a = tid; a < NPTS; a += THREADS) {
        float s = base[a];
#pragma unroll
        for (int t = 1; t < TCH; t++) s = fminf(s, base[(size_t)t * NPTS + a]);
        float x = Ap[3 * a + 0], y = Ap[3 * a + 1], z = Ap[3 * a + 2];
        sum += fmaf(x, x, fmaf(y, y, z * z)) + 2.0f * s;
    }
    s_red[tid] = sum;
    __syncthreads();
    for (int off = THREADS / 2; off > 0; off >>= 1) {
        if (tid < off) s_red[tid] += s_red[tid + off];
        __syncthreads();
    }

    if (tid == 0) {
        g_sums[dirb] = s_red[0];
        __threadfence();
        unsigned int old2 = atomicAdd(&g_cnt2, 1u);
        if (old2 == NDIRB - 1) {
            __threadfence();
            float total = 0.0f;
#pragma unroll
            for (int d = 0; d < NDIRB; d++) total += g_sums[d];
            *out = total * (1.0f / ((float)NB * (float)NPTS));
            // Reset counters for the next graph replay.
#pragma unroll
            for (int d = 0; d < NDIRB; d++) g_cnt[d] = 0u;
            g_cnt2 = 0u;
            __threadfence();
        }
    }
}

extern "C" void kernel_launch(void* const* d_in, const int* in_sizes, int n_in,
                              void* d_out, int out_size) {
    const float* pred = (const float*)d_in[0];
    const float* tgt  = (const float*)d_in[1];
    float* out = (float*)d_out;
    (void)in_sizes; (void)n_in; (void)out_size;

    dim3 grid(TCH, ACH, NDIRB);   // 8 x 8 x 8 = 512 CTAs
    chamfer_fused_kernel<<<grid, THREADS>>>(pred, tgt, out);
}